// round 3
// baseline (speedup 1.0000x reference)
#include <cuda_runtime.h>
#include <cuda_bf16.h>
#include <cstdint>

#define TAU_F 0.3f
#define EPS_F 1e-8f

static constexpr int NT   = 256;                  // threads per block
static constexpr int NB1  = 1024;                 // 4096 tiles / 1024 = exactly 4 tiles per CTA
static constexpr int TILE_BOXES = NT;             // 256 boxes per tile
static constexpr int TILE_F4    = TILE_BOXES * 7 / 4;  // 448 float4 per array per tile
static constexpr int FLOATS_PER_TILE = TILE_BOXES * 7;

__device__ float2       g_partials[NB1];
__device__ unsigned int g_done_count;             // zero-init; reset by last block each run

__device__ __forceinline__ float warp_sum(float v) {
    #pragma unroll
    for (int off = 16; off > 0; off >>= 1)
        v += __shfl_xor_sync(0xFFFFFFFFu, v, off);
    return v;
}

__device__ __forceinline__ void cp_async16(void* smem_ptr, const void* gmem_ptr) {
    uint32_t s = (uint32_t)__cvta_generic_to_shared(smem_ptr);
    asm volatile("cp.async.ca.shared.global [%0], [%1], 16;\n" :: "r"(s), "l"(gmem_ptr));
}

__global__ __launch_bounds__(NT) void gwd_fused(
    const float* __restrict__ pred,
    const float* __restrict__ gt,
    float* __restrict__ out,
    int total)
{
    __shared__ float4 sp[2][TILE_F4];
    __shared__ float4 sg[2][TILE_F4];

    const int ntiles = (total + TILE_BOXES - 1) / TILE_BOXES;
    const long long total_f = (long long)total * 7;

    // ---- tile loader: cp.async fast path, scalar fallback on ragged tail ----
    auto load_tile = [&](int buf, int tile) {
        const long long base = (long long)tile * FLOATS_PER_TILE;
        if (total_f - base >= FLOATS_PER_TILE) {
            const float4* p4 = (const float4*)(pred + base);
            const float4* g4 = (const float4*)(gt   + base);
            #pragma unroll
            for (int i = threadIdx.x; i < TILE_F4; i += NT) {
                cp_async16(&sp[buf][i], &p4[i]);
                cp_async16(&sg[buf][i], &g4[i]);
            }
        } else {
            float* spf = (float*)sp[buf];
            float* sgf = (float*)sg[buf];
            const int remain = (int)(total_f - base);
            for (int i = threadIdx.x; i < remain; i += NT) {
                spf[i] = pred[base + i];
                sgf[i] = gt[base + i];
            }
        }
    };

    float lsum = 0.0f;
    float msum = 0.0f;

    int tile = blockIdx.x;
    if (tile < ntiles) load_tile(0, tile);
    asm volatile("cp.async.commit_group;\n");

    for (int k = 0; tile < ntiles; tile += gridDim.x, k++) {
        const int next = tile + gridDim.x;
        if (next < ntiles) load_tile((k + 1) & 1, next);
        asm volatile("cp.async.commit_group;\n");

        // wait for current tile (allow the just-issued prefetch to stay in flight)
        if (next < ntiles) asm volatile("cp.async.wait_group 1;\n");
        else               asm volatile("cp.async.wait_group 0;\n");
        __syncthreads();

        const int buf = k & 1;
        const int box = tile * TILE_BOXES + threadIdx.x;
        if (box < total) {
            const float* p = (const float*)sp[buf] + 7 * threadIdx.x;
            const float* g = (const float*)sg[buf] + 7 * threadIdx.x;

            float p0 = p[0], p1 = p[1], p2 = p[2], p3 = p[3], p4v = p[4], p5 = p[5], p6 = p[6];
            float g0 = g[0], g1 = g[1], g2 = g[2], g3 = g[3], g4v = g[4], g5 = g[5], g6 = g[6];

            // ---- mean distance ----
            float dx = p0 - g0, dy = p1 - g1, dz = p2 - g2;
            float mu_dist = dx * dx + dy * dy + dz * dz;

            // ---- diagonal covariance eigenvalues ----
            float ap = 0.25f * p3 * p3, bp = 0.25f * p4v * p4v, cp = 0.25f * p5 * p5;
            float at = 0.25f * g3 * g3, bt = 0.25f * g4v * g4v, ct = 0.25f * g5 * g5;

            // sqrtm_psd(sigma_p) clips sigma_p eigenvalues at EPS
            float a = fmaxf(ap, EPS_F);
            float b = fmaxf(bp, EPS_F);
            float c = fmaxf(cp, EPS_F);

            // ---- 2x2 xy block of M = sqrt(Sp) St sqrt(Sp) ----
            float cd = __cosf(p6 - g6);
            float cc = cd * cd;
            float ss = 1.0f - cc;
            float trM  = cc * fmaf(a, at, b * bt) + ss * fmaf(a, bt, b * at);
            float detM = (a * b) * (at * bt);

            float disc = fmaxf(fmaf(trM, trM, -4.0f * detM), 0.0f);
            float sq   = sqrtf(disc);
            float l1   = fmaxf(0.5f * (trM + sq), EPS_F);
            float l2   = fmaxf(0.5f * (trM - sq), EPS_F);
            float tr_sqrtM = sqrtf(l1) + sqrtf(l2);

            // z scalar block
            float sz = sqrtf(fmaxf(c * ct, EPS_F));

            float cov = (ap + bp + cp) + (at + bt + ct) - 2.0f * (tr_sqrtM + sz);
            float w2  = mu_dist + cov;

            float detT  = fmaxf(at * bt * ct, EPS_F);
            float dterm = __expf(__logf(detT) * (1.0f / 3.0f));

            float loss = 1.0f - __expf(-w2 / (TAU_F * dterm));
            float mask = (g0 != 0.0f) ? 1.0f : 0.0f;

            lsum = fmaf(loss, mask, lsum);
            msum += mask;
        }
        __syncthreads();   // buffer safe to overwrite two iterations later
    }

    // ---- block reduction ----
    lsum = warp_sum(lsum);
    msum = warp_sum(msum);

    __shared__ float sl[NT / 32];
    __shared__ float sm[NT / 32];
    int lane = threadIdx.x & 31;
    int wid  = threadIdx.x >> 5;
    if (lane == 0) { sl[wid] = lsum; sm[wid] = msum; }
    __syncthreads();

    __shared__ bool is_last;
    if (threadIdx.x == 0) {
        float vl = 0.0f, vm = 0.0f;
        #pragma unroll
        for (int w = 0; w < NT / 32; w++) { vl += sl[w]; vm += sm[w]; }
        g_partials[blockIdx.x] = make_float2(vl, vm);
        __threadfence();
        unsigned int ticket = atomicAdd(&g_done_count, 1u);
        is_last = (ticket == (unsigned)(gridDim.x - 1));
    }
    __syncthreads();

    // ---- last block finalizes (deterministic order) ----
    if (is_last) {
        double l = 0.0, m = 0.0;
        for (int i = threadIdx.x; i < NB1; i += NT) {
            float2 v = g_partials[i];
            l += (double)v.x;
            m += (double)v.y;
        }
        #pragma unroll
        for (int off = 16; off > 0; off >>= 1) {
            l += __shfl_xor_sync(0xFFFFFFFFu, l, off);
            m += __shfl_xor_sync(0xFFFFFFFFu, m, off);
        }
        __shared__ double dl[NT / 32];
        __shared__ double dm[NT / 32];
        if (lane == 0) { dl[wid] = l; dm[wid] = m; }
        __syncthreads();
        if (threadIdx.x == 0) {
            double vl = 0.0, vm = 0.0;
            #pragma unroll
            for (int w = 0; w < NT / 32; w++) { vl += dl[w]; vm += dm[w]; }
            out[0] = (float)(vl / (vm + (double)EPS_F));
            g_done_count = 0;   // reset for next graph replay
        }
    }
}

extern "C" void kernel_launch(void* const* d_in, const int* in_sizes, int n_in,
                              void* d_out, int out_size)
{
    const float* pred = (const float*)d_in[0];
    const float* gt   = (const float*)d_in[1];
    float* out = (float*)d_out;

    int total = in_sizes[0] / 7;

    gwd_fused<<<NB1, NT>>>(pred, gt, out, total);
}

// round 4
// speedup vs baseline: 1.1215x; 1.1215x over previous
#include <cuda_runtime.h>
#include <cuda_bf16.h>
#include <cstdint>

#define TAU_INV   3.3333333333333335f   // 1/0.3
#define EPS_F     1e-8f
#define LOG2E_F   1.4426950408889634f

static constexpr int NT  = 256;
static constexpr int NB1 = 1184;                // 148 SMs * 8
static constexpr int FLOATS_PER_TILE = NT * 7;  // 1792 floats = 448 float4

__device__ float2       g_partials[NB1];
__device__ unsigned int g_done_count;

__device__ __forceinline__ float warp_sum(float v) {
    #pragma unroll
    for (int off = 16; off > 0; off >>= 1)
        v += __shfl_xor_sync(0xFFFFFFFFu, v, off);
    return v;
}

__device__ __forceinline__ float fsqrt_ap(float x) {
    float r; asm("sqrt.approx.f32 %0, %1;" : "=f"(r) : "f"(x)); return r;
}
__device__ __forceinline__ float ex2_ap(float x) {
    float r; asm("ex2.approx.f32 %0, %1;" : "=f"(r) : "f"(x)); return r;
}
__device__ __forceinline__ float lg2_ap(float x) {
    float r; asm("lg2.approx.f32 %0, %1;" : "=f"(r) : "f"(x)); return r;
}

__global__ __launch_bounds__(NT) void gwd_fused(
    const float* __restrict__ pred,
    const float* __restrict__ gt,
    float* __restrict__ out,
    int total)
{
    __shared__ float sp[FLOATS_PER_TILE];
    __shared__ float sg[FLOATS_PER_TILE];

    const int ntiles = (total + NT - 1) / NT;
    const long long total_f = (long long)total * 7;

    float lsum = 0.0f;
    float msum = 0.0f;

    for (int tile = blockIdx.x; tile < ntiles; tile += gridDim.x) {
        const long long base = (long long)tile * FLOATS_PER_TILE;

        if (total_f - base >= FLOATS_PER_TILE) {
            // full tile: coalesced LDG.128 -> STS.128
            const float4* __restrict__ p4 = (const float4*)(pred + base);
            const float4* __restrict__ g4 = (const float4*)(gt   + base);
            float4* sp4 = (float4*)sp;
            float4* sg4 = (float4*)sg;
            #pragma unroll
            for (int i = threadIdx.x; i < FLOATS_PER_TILE / 4; i += NT) {
                sp4[i] = p4[i];
                sg4[i] = g4[i];
            }
        } else {
            const int remain = (int)(total_f - base);
            for (int i = threadIdx.x; i < remain; i += NT) {
                sp[i] = pred[base + i];
                sg[i] = gt[base + i];
            }
        }
        __syncthreads();

        const int box = tile * NT + threadIdx.x;
        if (box < total) {
            const float* p = sp + 7 * threadIdx.x;
            const float* g = sg + 7 * threadIdx.x;

            float p0 = p[0], p1 = p[1], p2 = p[2], p3 = p[3], p4v = p[4], p5 = p[5], p6 = p[6];
            float g0 = g[0], g1 = g[1], g2 = g[2], g3 = g[3], g4v = g[4], g5 = g[5], g6 = g[6];

            // mean distance
            float dx = p0 - g0, dy = p1 - g1, dz = p2 - g2;
            float mu_dist = fmaf(dx, dx, fmaf(dy, dy, dz * dz));

            // diagonal covariance eigenvalues
            float ap = 0.25f * p3 * p3, bp = 0.25f * p4v * p4v, cp = 0.25f * p5 * p5;
            float at = 0.25f * g3 * g3, bt = 0.25f * g4v * g4v, ct = 0.25f * g5 * g5;

            // sigma_p eigenvalue clip (from first sqrtm_psd)
            float a = fmaxf(ap, EPS_F);
            float b = fmaxf(bp, EPS_F);
            float c = fmaxf(cp, EPS_F);

            // 2x2 xy block of M = sqrt(Sp) St sqrt(Sp)
            float cd = __cosf(p6 - g6);
            float cc = cd * cd;
            float ss = 1.0f - cc;
            float S1 = fmaf(a, at, b * bt);
            float S2 = fmaf(a, bt, b * at);
            float trM  = fmaf(cc, S1, ss * S2);
            float detM = (a * b) * (at * bt);

            // sqrt(l1)+sqrt(l2) = sqrt(trM + 2*sqrt(detM)) (M PSD)
            float tr_sqrtM = fsqrt_ap(fmaf(2.0f, fsqrt_ap(detM), trM));

            // z scalar block
            float sz = fsqrt_ap(fmaxf(c * ct, EPS_F));

            float cov = ((ap + bp + cp) + (at + bt + ct)) - 2.0f * (tr_sqrtM + sz);
            float w2  = mu_dist + cov;

            // det term: 1/(TAU * detT^(1/3)) = (1/TAU) * ex2(-lg2(detT)/3)
            float detT  = fmaxf(at * bt * ct, EPS_F);
            float inv_d = ex2_ap(lg2_ap(detT) * (-1.0f / 3.0f)) * TAU_INV;

            // loss = 1 - exp(-w2 * inv_d)
            float loss = 1.0f - ex2_ap(-w2 * inv_d * LOG2E_F);
            float mask = (g0 != 0.0f) ? 1.0f : 0.0f;

            lsum = fmaf(loss, mask, lsum);
            msum += mask;
        }
        __syncthreads();
    }

    // block reduction
    lsum = warp_sum(lsum);
    msum = warp_sum(msum);

    __shared__ float sl[NT / 32];
    __shared__ float sm[NT / 32];
    int lane = threadIdx.x & 31;
    int wid  = threadIdx.x >> 5;
    if (lane == 0) { sl[wid] = lsum; sm[wid] = msum; }
    __syncthreads();

    __shared__ bool is_last;
    if (threadIdx.x == 0) {
        float vl = 0.0f, vm = 0.0f;
        #pragma unroll
        for (int w = 0; w < NT / 32; w++) { vl += sl[w]; vm += sm[w]; }
        g_partials[blockIdx.x] = make_float2(vl, vm);
        __threadfence();
        unsigned int ticket = atomicAdd(&g_done_count, 1u);
        is_last = (ticket == (unsigned)(gridDim.x - 1));
    }
    __syncthreads();

    // last block finalizes (deterministic order)
    if (is_last) {
        double l = 0.0, m = 0.0;
        for (int i = threadIdx.x; i < NB1; i += NT) {
            float2 v = g_partials[i];
            l += (double)v.x;
            m += (double)v.y;
        }
        #pragma unroll
        for (int off = 16; off > 0; off >>= 1) {
            l += __shfl_xor_sync(0xFFFFFFFFu, l, off);
            m += __shfl_xor_sync(0xFFFFFFFFu, m, off);
        }
        __shared__ double dl[NT / 32];
        __shared__ double dm[NT / 32];
        if (lane == 0) { dl[wid] = l; dm[wid] = m; }
        __syncthreads();
        if (threadIdx.x == 0) {
            double vl = 0.0, vm = 0.0;
            #pragma unroll
            for (int w = 0; w < NT / 32; w++) { vl += dl[w]; vm += dm[w]; }
            out[0] = (float)(vl / (vm + (double)EPS_F));
            g_done_count = 0;   // reset for next graph replay
        }
    }
}

extern "C" void kernel_launch(void* const* d_in, const int* in_sizes, int n_in,
                              void* d_out, int out_size)
{
    const float* pred = (const float*)d_in[0];
    const float* gt   = (const float*)d_in[1];
    float* out = (float*)d_out;

    int total = in_sizes[0] / 7;

    gwd_fused<<<NB1, NT>>>(pred, gt, out, total);
}